// round 14
// baseline (speedup 1.0000x reference)
#include <cuda_runtime.h>
#include <cstdint>

// ---------------------------------------------------------------------------
// B=2, S=2048, D_MODEL=2048, N_HEADS=32, N_KV_HEADS=8, D_HEAD=64, T=4096
// ---------------------------------------------------------------------------
#define T_TOK 4096
#define DMODEL 2048
#define NH 32
#define NKV 8
#define DH 64
#define SEQ 2048

// scratch
__device__ float g_Q[(size_t)T_TOK * (NH * DH)];
__device__ float g_K[(size_t)T_TOK * (NKV * DH)];
__device__ float g_V[(size_t)T_TOK * (NKV * DH)];
__device__ float g_AO[(size_t)T_TOK * (NH * DH)];
__device__ float g_RES[(size_t)T_TOK * DMODEL];
__device__ float g_WQr[(size_t)NH * DH * DMODEL];
__device__ float g_WKr[(size_t)NKV * DH * DMODEL];
__device__ float g_WVr[(size_t)NKV * DH * DMODEL];
__device__ float g_WOr[(size_t)NH * DH * DMODEL];

// ---------------------------------------------------------------------------
// helpers
// ---------------------------------------------------------------------------
__device__ __forceinline__ uint32_t f2tf32(float x) {
    uint32_t r;
    asm("cvt.rna.tf32.f32 %0, %1;" : "=r"(r) : "f"(x));
    return r;
}

__device__ __forceinline__ uint32_t smem_u32(const void* p) {
    uint32_t a;
    asm("{ .reg .u64 t; cvta.to.shared.u64 t, %1; cvt.u32.u64 %0, t; }"
        : "=r"(a) : "l"(p));
    return a;
}

__device__ __forceinline__ void cp_async16(uint32_t dst, const void* src) {
    asm volatile("cp.async.cg.shared.global [%0], [%1], 16;"
                 :: "r"(dst), "l"(src));
}
#define CP_COMMIT() asm volatile("cp.async.commit_group;" ::: "memory")
#define CP_WAIT(n)  asm volatile("cp.async.wait_group %0;" :: "n"(n) : "memory")

__device__ __forceinline__ void mma_tf32(float c[4], uint32_t a0, uint32_t a1,
                                         uint32_t a2, uint32_t a3,
                                         uint32_t b0, uint32_t b1) {
    asm volatile(
        "mma.sync.aligned.m16n8k8.row.col.f32.tf32.tf32.f32 "
        "{%0,%1,%2,%3}, {%4,%5,%6,%7}, {%8,%9}, {%0,%1,%2,%3};"
        : "+f"(c[0]), "+f"(c[1]), "+f"(c[2]), "+f"(c[3])
        : "r"(a0), "r"(a1), "r"(a2), "r"(a3), "r"(b0), "r"(b1));
}

// ---------------------------------------------------------------------------
// Fused tf32 pre-round for all 5 inputs in one launch.
// Block ranges: [0,8192) residual, [8192,12288) WQ, [12288,13312) WK,
// [13312,14336) WV, [14336,18432) WO.  1024 floats per block.
// ---------------------------------------------------------------------------
__global__ __launch_bounds__(256)
void round5_tf32(const float* __restrict__ iR, const float* __restrict__ iQ,
                 const float* __restrict__ iK, const float* __restrict__ iV,
                 const float* __restrict__ iO,
                 float* __restrict__ oR, float* __restrict__ oQ,
                 float* __restrict__ oK, float* __restrict__ oV,
                 float* __restrict__ oO) {
    int b = blockIdx.x;
    const float* in;
    float* out;
    size_t base;
    if (b < 8192)       { in = iR; out = oR; base = (size_t)b * 1024; }
    else if (b < 12288) { in = iQ; out = oQ; base = (size_t)(b - 8192) * 1024; }
    else if (b < 13312) { in = iK; out = oK; base = (size_t)(b - 12288) * 1024; }
    else if (b < 14336) { in = iV; out = oV; base = (size_t)(b - 13312) * 1024; }
    else                { in = iO; out = oO; base = (size_t)(b - 14336) * 1024; }
    size_t i = base + (size_t)threadIdx.x * 4;
    float4 v = *(const float4*)(in + i);
    uint4 u = {f2tf32(v.x), f2tf32(v.y), f2tf32(v.z), f2tf32(v.w)};
    *(float4*)(out + i) = *(float4*)&u;
}

// ---------------------------------------------------------------------------
// Fused QKV tf32 GEMM (NT), cp.async, double-buffered.
// ---------------------------------------------------------------------------
#define GLDA 36
#define ABUF (128 * GLDA)

__global__ __launch_bounds__(256)
void gemm_qkv_tf32(const float* __restrict__ A,
                   const float* __restrict__ WQ, const float* __restrict__ WK,
                   const float* __restrict__ WV,
                   float* __restrict__ Qo, float* __restrict__ Ko,
                   float* __restrict__ Vo) {
    extern __shared__ uint32_t sm[];
    uint32_t* As = sm;
    uint32_t* Bs = sm + 2 * ABUF;
    const uint32_t saA = smem_u32(sm);
    const uint32_t saB = saA + 2 * ABUF * 4;

    const int bx = blockIdx.x;
    const float* Bmat;
    float* C;
    int N, cb0;
    if (bx < 16)      { Bmat = WQ; C = Qo; N = 2048; cb0 = bx; }
    else if (bx < 20) { Bmat = WK; C = Ko; N = 512;  cb0 = bx - 16; }
    else              { Bmat = WV; C = Vo; N = 512;  cb0 = bx - 20; }

    const int Kd = DMODEL;
    const int tid = threadIdx.x, lane = tid & 31, wid = tid >> 5;
    const int wm = wid >> 2, wn = wid & 3;
    const int lg = lane >> 2, lt = lane & 3;

    const float* Ab = A + (size_t)(blockIdx.y * 128) * Kd;
    const float* Bb = Bmat + (size_t)cb0 * 128 * Kd;

    float acc[4][4][4];
#pragma unroll
    for (int i = 0; i < 4; i++)
#pragma unroll
        for (int j = 0; j < 4; j++)
#pragma unroll
            for (int r = 0; r < 4; r++) acc[i][j][r] = 0.f;

#define ISSUE(k0, buf)                                                          \
    {                                                                           \
        _Pragma("unroll") for (int i = 0; i < 4; i++) {                         \
            int idx = tid + i * 256;                                            \
            int rw = idx >> 3, cq = (idx & 7) * 4;                              \
            uint32_t so = (uint32_t)(rw * GLDA + cq) * 4;                       \
            cp_async16(saA + (buf) * (ABUF * 4) + so,                           \
                       Ab + (size_t)rw * Kd + (k0) + cq);                       \
            cp_async16(saB + (buf) * (ABUF * 4) + so,                           \
                       Bb + (size_t)rw * Kd + (k0) + cq);                       \
        }                                                                       \
    }

    ISSUE(0, 0); CP_COMMIT();

    const int nsteps = Kd / 32;
    for (int t = 0; t < nsteps; t++) {
        if (t + 1 < nsteps) { ISSUE((t + 1) * 32, (t + 1) & 1); CP_COMMIT(); CP_WAIT(1); }
        else                { CP_WAIT(0); }
        __syncthreads();

        const uint32_t* Acur = &As[(t & 1) * ABUF];
        const uint32_t* Bcur = &Bs[(t & 1) * ABUF];
#pragma unroll
        for (int ks = 0; ks < 4; ks++) {
            uint32_t af[4][4];
#pragma unroll
            for (int mi = 0; mi < 4; mi++) {
                int r = wm * 64 + mi * 16 + lg, c = ks * 8 + lt;
                af[mi][0] = Acur[r * GLDA + c];
                af[mi][1] = Acur[(r + 8) * GLDA + c];
                af[mi][2] = Acur[r * GLDA + c + 4];
                af[mi][3] = Acur[(r + 8) * GLDA + c + 4];
            }
#pragma unroll
            for (int ni = 0; ni < 4; ni++) {
                int cb = wn * 32 + ni * 8 + lg, ck = ks * 8 + lt;
                uint32_t b0 = Bcur[cb * GLDA + ck];
                uint32_t b1 = Bcur[cb * GLDA + ck + 4];
#pragma unroll
                for (int mi = 0; mi < 4; mi++)
                    mma_tf32(acc[mi][ni], af[mi][0], af[mi][1], af[mi][2], af[mi][3], b0, b1);
            }
        }
        __syncthreads();
    }
#undef ISSUE

    // epilogue: tf32-rounded outputs (consumed as tf32 by attention)
#pragma unroll
    for (int mi = 0; mi < 4; mi++) {
        int row = blockIdx.y * 128 + wm * 64 + mi * 16 + lg;
#pragma unroll
        for (int ni = 0; ni < 4; ni++) {
            int col = cb0 * 128 + wn * 32 + ni * 8 + lt * 2;
            uint2 u0 = {f2tf32(acc[mi][ni][0]), f2tf32(acc[mi][ni][1])};
            uint2 u1 = {f2tf32(acc[mi][ni][2]), f2tf32(acc[mi][ni][3])};
            *(uint2*)(C + (size_t)row * N + col) = u0;
            *(uint2*)(C + (size_t)(row + 8) * N + col) = u1;
        }
    }
}

// ---------------------------------------------------------------------------
// tf32 GEMM NN, cp.async: C = A * B.
// ---------------------------------------------------------------------------
#define GLDB 132
#define BBUF (32 * GLDB)

__global__ __launch_bounds__(256)
void gemm_nn_tf32(const float* __restrict__ A, const float* __restrict__ B,
                  float* __restrict__ C, int M, int N, int K) {
    extern __shared__ uint32_t sm[];
    uint32_t* As = sm;
    uint32_t* Bs = sm + 2 * ABUF;
    const uint32_t saA = smem_u32(sm);
    const uint32_t saB = saA + 2 * ABUF * 4;

    const int tid = threadIdx.x, lane = tid & 31, wid = tid >> 5;
    const int wm = wid >> 2, wn = wid & 3;
    const int lg = lane >> 2, lt = lane & 3;

    const float* Ab = A + (size_t)(blockIdx.y * 128) * K;
    const float* Bb = B + blockIdx.x * 128;

    float acc[4][4][4];
#pragma unroll
    for (int i = 0; i < 4; i++)
#pragma unroll
        for (int j = 0; j < 4; j++)
#pragma unroll
            for (int r = 0; r < 4; r++) acc[i][j][r] = 0.f;

#define ISSUE(k0, buf)                                                          \
    {                                                                           \
        _Pragma("unroll") for (int i = 0; i < 4; i++) {                         \
            int idx = tid + i * 256;                                            \
            int rw = idx >> 3, cq = (idx & 7) * 4;                              \
            cp_async16(saA + (buf) * (ABUF * 4) + (uint32_t)(rw * GLDA + cq) * 4, \
                       Ab + (size_t)rw * K + (k0) + cq);                        \
            int bk = idx >> 5, bc = (idx & 31) * 4;                             \
            cp_async16(saB + (buf) * (BBUF * 4) + (uint32_t)(bk * GLDB + bc) * 4, \
                       Bb + (size_t)((k0) + bk) * N + bc);                      \
        }                                                                       \
    }

    ISSUE(0, 0); CP_COMMIT();

    const int nsteps = K / 32;
    for (int t = 0; t < nsteps; t++) {
        if (t + 1 < nsteps) { ISSUE((t + 1) * 32, (t + 1) & 1); CP_COMMIT(); CP_WAIT(1); }
        else                { CP_WAIT(0); }
        __syncthreads();

        const uint32_t* Acur = &As[(t & 1) * ABUF];
        const uint32_t* Bcur = &Bs[(t & 1) * BBUF];
#pragma unroll
        for (int ks = 0; ks < 4; ks++) {
            uint32_t af[4][4];
#pragma unroll
            for (int mi = 0; mi < 4; mi++) {
                int r = wm * 64 + mi * 16 + lg, c = ks * 8 + lt;
                af[mi][0] = Acur[r * GLDA + c];
                af[mi][1] = Acur[(r + 8) * GLDA + c];
                af[mi][2] = Acur[r * GLDA + c + 4];
                af[mi][3] = Acur[(r + 8) * GLDA + c + 4];
            }
#pragma unroll
            for (int ni = 0; ni < 4; ni++) {
                int cn = wn * 32 + ni * 8 + lg;
                uint32_t b0 = Bcur[(ks * 8 + lt) * GLDB + cn];
                uint32_t b1 = Bcur[(ks * 8 + lt + 4) * GLDB + cn];
#pragma unroll
                for (int mi = 0; mi < 4; mi++)
                    mma_tf32(acc[mi][ni], af[mi][0], af[mi][1], af[mi][2], af[mi][3], b0, b1);
            }
        }
        __syncthreads();
    }
#undef ISSUE

#pragma unroll
    for (int mi = 0; mi < 4; mi++) {
        int row = blockIdx.y * 128 + wm * 64 + mi * 16 + lg;
#pragma unroll
        for (int ni = 0; ni < 4; ni++) {
            int col = blockIdx.x * 128 + wn * 32 + ni * 8 + lt * 2;
            *(float2*)(C + (size_t)row * N + col) = make_float2(acc[mi][ni][0], acc[mi][ni][1]);
            *(float2*)(C + (size_t)(row + 8) * N + col) = make_float2(acc[mi][ni][2], acc[mi][ni][3]);
        }
    }
}

// ---------------------------------------------------------------------------
// Flash attention, tf32 mma.sync. BM=128 Q rows, K tile 64.
// DOUBLE-BUFFERED cp.async K/V: tile kt+1 in flight during tile kt compute.
// Base-2 softmax: Q pre-scaled by 0.125*log2(e); exp -> exp2 (bare EX2).
// SMEM: Ks[2][64][68] Vs[2][64][68] Ps[128][68] = 104,448 B -> 2 CTAs/SM
// (reg-limited: 2 x 256thr x 128regs = 64K). LPT block order.
// ---------------------------------------------------------------------------
#define ALDS 68
#define KVT (64 * ALDS)
#define KVTB (KVT * 4)
#define NEG_BIG (-1e30f)
#define QSCALE 0.18033688011112042f   /* 0.125 * log2(e) */

__global__ __launch_bounds__(256, 2)
void attn_tf32(const float* __restrict__ Q, const float* __restrict__ K,
               const float* __restrict__ V, float* __restrict__ O) {
    extern __shared__ uint32_t sm[];
    // layout: Ks0 | Ks1 | Vs0 | Vs1 | Ps
    uint32_t* Ps = sm + 4 * KVT;
    const uint32_t ksA = smem_u32(sm);
    const uint32_t vsA = ksA + 2 * KVTB;

    const int qt = gridDim.x - 1 - blockIdx.x;   // LPT: heavy first
    const int h = blockIdx.y, b = blockIdx.z;
    const int kvh = h >> 2;
    const int tid = threadIdx.x, lane = tid & 31, wid = tid >> 5;
    const int lg = lane >> 2, lt = lane & 3;
    const int q0 = wid * 16;

    const float* Qg = Q + ((size_t)(b * SEQ + qt * 128)) * (NH * DH) + h * DH;
    const float* Kg = K + ((size_t)b * SEQ) * (NKV * DH) + kvh * DH;
    const float* Vg = V + ((size_t)b * SEQ) * (NKV * DH) + kvh * DH;

    const int ldr = tid >> 4;            // 0..15
    const int ldc = (tid & 15) * 4;      // 16B-aligned word col

    // Q fragments: pre-rounded tf32 * (0.125*log2e), re-rounded (prologue only)
    uint32_t qf[8][4];
    {
        const float* q0p = Qg + (size_t)(q0 + lg) * (NH * DH);
        const float* q1p = Qg + (size_t)(q0 + lg + 8) * (NH * DH);
#pragma unroll
        for (int ks = 0; ks < 8; ks++) {
            int c = ks * 8 + lt;
            qf[ks][0] = f2tf32(__ldg(q0p + c) * QSCALE);
            qf[ks][1] = f2tf32(__ldg(q1p + c) * QSCALE);
            qf[ks][2] = f2tf32(__ldg(q0p + c + 4) * QSCALE);
            qf[ks][3] = f2tf32(__ldg(q1p + c + 4) * QSCALE);
        }
    }

    float m0 = NEG_BIG, m1 = NEG_BIG, l0 = 0.f, l1 = 0.f;
    float acc[8][4];
#pragma unroll
    for (int d = 0; d < 8; d++)
#pragma unroll
        for (int r = 0; r < 4; r++) acc[d][r] = 0.f;

    const int ktmax = 2 * qt + 1;
    const int warp_qlast = qt * 128 + q0 + 15;

#define ISSUE_KV(kt_, buf_)                                                     \
    {                                                                           \
        _Pragma("unroll") for (int i = 0; i < 4; i++) {                         \
            int r = ldr + i * 16;                                               \
            uint32_t so = (uint32_t)(r * ALDS + ldc) * 4;                       \
            cp_async16(ksA + (buf_) * KVTB + so,                                \
                       Kg + (size_t)((kt_) * 64 + r) * (NKV * DH) + ldc);       \
            cp_async16(vsA + (buf_) * KVTB + so,                                \
                       Vg + (size_t)((kt_) * 64 + r) * (NKV * DH) + ldc);       \
        }                                                                       \
    }

    ISSUE_KV(0, 0); CP_COMMIT();

    for (int kt = 0; kt <= ktmax; kt++) {
        const int bsel = kt & 1;
        if (kt < ktmax) { ISSUE_KV(kt + 1, bsel ^ 1); CP_COMMIT(); CP_WAIT(1); }
        else            { CP_WAIT(0); }
        __syncthreads();     // tile kt visible to all warps

        const uint32_t* Kb = sm + bsel * KVT;
        const uint32_t* Vb = sm + 2 * KVT + bsel * KVT;

        if (kt * 64 <= warp_qlast) {      // tile not fully masked for this warp
            float sc[8][4];
#pragma unroll
            for (int ni = 0; ni < 8; ni++)
#pragma unroll
                for (int r = 0; r < 4; r++) sc[ni][r] = 0.f;
#pragma unroll
            for (int ks = 0; ks < 8; ks++) {
#pragma unroll
                for (int ni = 0; ni < 8; ni++) {
                    int rB = ni * 8 + lg, cB = ks * 8 + lt;
                    uint32_t b0 = Kb[rB * ALDS + cB];
                    uint32_t b1 = Kb[rB * ALDS + cB + 4];
                    mma_tf32(sc[ni], qf[ks][0], qf[ks][1], qf[ks][2], qf[ks][3], b0, b1);
                }
            }

            if (kt * 64 + 63 > qt * 128 + q0) {   // diagonal: causal mask
                int r0g = qt * 128 + q0 + lg, r1g = r0g + 8;
#pragma unroll
                for (int ni = 0; ni < 8; ni++) {
                    int cg = kt * 64 + ni * 8 + lt * 2;
                    if (cg > r0g) sc[ni][0] = NEG_BIG;
                    if (cg + 1 > r0g) sc[ni][1] = NEG_BIG;
                    if (cg > r1g) sc[ni][2] = NEG_BIG;
                    if (cg + 1 > r1g) sc[ni][3] = NEG_BIG;
                }
            }

            // online softmax in base-2: rows (q0+lg), (q0+lg+8)
            float mx0 = NEG_BIG, mx1 = NEG_BIG;
#pragma unroll
            for (int ni = 0; ni < 8; ni++) {
                mx0 = fmaxf(mx0, fmaxf(sc[ni][0], sc[ni][1]));
                mx1 = fmaxf(mx1, fmaxf(sc[ni][2], sc[ni][3]));
            }
            mx0 = fmaxf(mx0, __shfl_xor_sync(0xffffffffu, mx0, 1));
            mx0 = fmaxf(mx0, __shfl_xor_sync(0xffffffffu, mx0, 2));
            mx1 = fmaxf(mx1, __shfl_xor_sync(0xffffffffu, mx1, 1));
            mx1 = fmaxf(mx1, __shfl_xor_sync(0xffffffffu, mx1, 2));
            float nm0 = fmaxf(m0, mx0), nm1 = fmaxf(m1, mx1);
            float corr0 = exp2f(m0 - nm0), corr1 = exp2f(m1 - nm1);
            m0 = nm0; m1 = nm1;

            float s0 = 0.f, s1 = 0.f;
            int pr0 = (q0 + lg) * ALDS, pr1 = (q0 + lg + 8) * ALDS;
#pragma unroll
            for (int ni = 0; ni < 8; ni++) {
                int c = ni * 8 + lt * 2;
                float p00 = exp2f(sc[ni][0] - m0), p01 = exp2f(sc[ni][1] - m0);
                float p10 = exp2f(sc[ni][2] - m1), p11 = exp2f(sc[ni][3] - m1);
                s0 += p00 + p01; s1 += p10 + p11;
                uint2 u0 = {f2tf32(p00), f2tf32(p01)};
                uint2 u1 = {f2tf32(p10), f2tf32(p11)};
                *(uint2*)&Ps[pr0 + c] = u0;
                *(uint2*)&Ps[pr1 + c] = u1;
            }
            s0 += __shfl_xor_sync(0xffffffffu, s0, 1);
            s0 += __shfl_xor_sync(0xffffffffu, s0, 2);
            s1 += __shfl_xor_sync(0xffffffffu, s1, 1);
            s1 += __shfl_xor_sync(0xffffffffu, s1, 2);
            l0 = l0 * corr0 + s0;
            l1 = l1 * corr1 + s1;
#pragma unroll
            for (int d = 0; d < 8; d++) {
                acc[d][0] *= corr0; acc[d][1] *= corr0;
                acc[d][2] *= corr1; acc[d][3] *= corr1;
            }
            __syncwarp();

            // acc += P V  (P rows warp-private)
#pragma unroll
            for (int ks = 0; ks < 8; ks++) {
                int rA = q0 + lg, cA = ks * 8 + lt;
                uint32_t a0 = Ps[rA * ALDS + cA];
                uint32_t a1 = Ps[(rA + 8) * ALDS + cA];
                uint32_t a2 = Ps[rA * ALDS + cA + 4];
                uint32_t a3 = Ps[(rA + 8) * ALDS + cA + 4];
#pragma unroll
                for (int di = 0; di < 8; di++) {
                    int cn = di * 8 + lg;
                    uint32_t b0 = Vb[(ks * 8 + lt) * ALDS + cn];
                    uint32_t b1 = Vb[(ks * 8 + lt + 4) * ALDS + cn];
                    mma_tf32(acc[di], a0, a1, a2, a3, b0, b1);
                }
            }
        }
        __syncthreads();   // close reads of buffer bsel before reissue
    }
#undef ISSUE_KV

    // epilogue: normalize, round to tf32 (feeds the O-projection)
    float inv0 = 1.f / l0, inv1 = 1.f / l1;
    float* Og = O + ((size_t)(b * SEQ + qt * 128 + q0 + lg)) * (NH * DH) + h * DH;
#pragma unroll
    for (int di = 0; di < 8; di++) {
        int c = di * 8 + lt * 2;
        uint2 u0 = {f2tf32(acc[di][0] * inv0), f2tf32(acc[di][1] * inv0)};
        uint2 u1 = {f2tf32(acc[di][2] * inv1), f2tf32(acc[di][3] * inv1)};
        *(uint2*)(Og + c) = u0;
        *(uint2*)(Og + (size_t)8 * (NH * DH) + c) = u1;
    }
}

// ---------------------------------------------------------------------------
// kernel_launch
// ---------------------------------------------------------------------------
extern "C" void kernel_launch(void* const* d_in, const int* in_sizes, int n_in,
                              void* d_out, int out_size) {
    const float* residual = (const float*)d_in[0];
    const float* WQ = (const float*)d_in[1];
    const float* WK = (const float*)d_in[2];
    const float* WV = (const float*)d_in[3];
    const float* WO = (const float*)d_in[4];
    float* out = (float*)d_out;

    float *Qb, *Kb, *Vb, *AOb, *RESb, *WQb, *WKb, *WVb, *WOb;
    cudaGetSymbolAddress((void**)&Qb, g_Q);
    cudaGetSymbolAddress((void**)&Kb, g_K);
    cudaGetSymbolAddress((void**)&Vb, g_V);
    cudaGetSymbolAddress((void**)&AOb, g_AO);
    cudaGetSymbolAddress((void**)&RESb, g_RES);
    cudaGetSymbolAddress((void**)&WQb, g_WQr);
    cudaGetSymbolAddress((void**)&WKb, g_WKr);
    cudaGetSymbolAddress((void**)&WVb, g_WVr);
    cudaGetSymbolAddress((void**)&WOb, g_WOr);

    size_t smem_nt = (size_t)4 * ABUF * 4;
    size_t smem_nn = ((size_t)2 * ABUF + 2 * BBUF) * 4;
    size_t smem_at = ((size_t)4 * KVT + 128 * ALDS) * 4;   // 104,448 B
    static int attrs_set = 0;
    if (!attrs_set) {
        cudaFuncSetAttribute(gemm_qkv_tf32, cudaFuncAttributeMaxDynamicSharedMemorySize, (int)smem_nt);
        cudaFuncSetAttribute(gemm_nn_tf32, cudaFuncAttributeMaxDynamicSharedMemorySize, (int)smem_nn);
        cudaFuncSetAttribute(attn_tf32, cudaFuncAttributeMaxDynamicSharedMemorySize, (int)smem_at);
        attrs_set = 1;
    }

    // single fused tf32 pre-round pass for all inputs
    round5_tf32<<<18432, 256>>>(residual, WQ, WK, WV, WO,
                                RESb, WQb, WKb, WVb, WOb);

    gemm_qkv_tf32<<<dim3(24, T_TOK / 128), 256, smem_nt>>>(
        RESb, WQb, WKb, WVb, Qb, Kb, Vb);

    attn_tf32<<<dim3(SEQ / 128, NH, 2), 256, smem_at>>>(Qb, Kb, Vb, AOb);

    gemm_nn_tf32<<<dim3(DMODEL / 128, T_TOK / 128), 256, smem_nn>>>(
        AOb, WOb, out, T_TOK, DMODEL, DMODEL);
}

// round 15
// speedup vs baseline: 1.1431x; 1.1431x over previous
#include <cuda_runtime.h>
#include <cstdint>

// ---------------------------------------------------------------------------
// B=2, S=2048, D_MODEL=2048, N_HEADS=32, N_KV_HEADS=8, D_HEAD=64, T=4096
// ---------------------------------------------------------------------------
#define T_TOK 4096
#define DMODEL 2048
#define NH 32
#define NKV 8
#define DH 64
#define SEQ 2048

// scratch
__device__ float g_Q[(size_t)T_TOK * (NH * DH)];
__device__ float g_K[(size_t)T_TOK * (NKV * DH)];
__device__ float g_V[(size_t)T_TOK * (NKV * DH)];
__device__ float g_Vt[(size_t)2 * (NKV * DH) * SEQ];    // [b][feat][tok]
__device__ float g_AO[(size_t)T_TOK * (NH * DH)];
__device__ float g_RES[(size_t)T_TOK * DMODEL];
__device__ float g_WQr[(size_t)NH * DH * DMODEL];
__device__ float g_WKr[(size_t)NKV * DH * DMODEL];
__device__ float g_WVr[(size_t)NKV * DH * DMODEL];
__device__ float g_WOt[(size_t)DMODEL * DMODEL];        // W_O^T, tf32-rounded

// ---------------------------------------------------------------------------
// helpers
// ---------------------------------------------------------------------------
__device__ __forceinline__ uint32_t f2tf32(float x) {
    uint32_t r;
    asm("cvt.rna.tf32.f32 %0, %1;" : "=r"(r) : "f"(x));
    return r;
}

__device__ __forceinline__ uint32_t smem_u32(const void* p) {
    uint32_t a;
    asm("{ .reg .u64 t; cvta.to.shared.u64 t, %1; cvt.u32.u64 %0, t; }"
        : "=r"(a) : "l"(p));
    return a;
}

__device__ __forceinline__ void cp_async16(uint32_t dst, const void* src) {
    asm volatile("cp.async.cg.shared.global [%0], [%1], 16;"
                 :: "r"(dst), "l"(src));
}
#define CP_COMMIT() asm volatile("cp.async.commit_group;" ::: "memory")
#define CP_WAIT(n)  asm volatile("cp.async.wait_group %0;" :: "n"(n) : "memory")

__device__ __forceinline__ void mma_tf32(float c[4], uint32_t a0, uint32_t a1,
                                         uint32_t a2, uint32_t a3,
                                         uint32_t b0, uint32_t b1) {
    asm volatile(
        "mma.sync.aligned.m16n8k8.row.col.f32.tf32.tf32.f32 "
        "{%0,%1,%2,%3}, {%4,%5,%6,%7}, {%8,%9}, {%0,%1,%2,%3};"
        : "+f"(c[0]), "+f"(c[1]), "+f"(c[2]), "+f"(c[3])
        : "r"(a0), "r"(a1), "r"(a2), "r"(a3), "r"(b0), "r"(b1));
}

// ldmatrix x4 on 32-bit (tf32) data viewed as b16 pairs. Address per thread.
__device__ __forceinline__ void ldsm4(uint32_t d[4], uint32_t addr) {
    asm volatile("ldmatrix.sync.aligned.m8n8.x4.shared.b16 {%0,%1,%2,%3}, [%4];"
                 : "=r"(d[0]), "=r"(d[1]), "=r"(d[2]), "=r"(d[3]) : "r"(addr));
}

// Per-thread LDSM address pieces.
// A-pattern (m16 x k8 frag -> regs a0,a1,a2,a3):
//   row = r0 + arow, colword = kc + acol
//   arow = (ln&7) + ((ln>>3)&1)*8 ; acol = (ln>>4)*4
// B-pattern (two n8 x k8 frags, n-major rows -> b0(n0),b1(n0),b0(n1),b1(n1)):
//   row = nb + brow, colword = kc + bcol
//   brow = (ln&7) + (ln>>4)*8 ; bcol = ((ln>>3)&1)*4

// ---------------------------------------------------------------------------
// Fused tf32 pre-round: residual, WQ, WK, WV (WO handled by trans_wo).
// Block ranges: [0,8192) R, [8192,12288) WQ, [12288,13312) WK, [13312,14336) WV
// ---------------------------------------------------------------------------
__global__ __launch_bounds__(256)
void round4_tf32(const float* __restrict__ iR, const float* __restrict__ iQ,
                 const float* __restrict__ iK, const float* __restrict__ iV,
                 float* __restrict__ oR, float* __restrict__ oQ,
                 float* __restrict__ oK, float* __restrict__ oV) {
    int b = blockIdx.x;
    const float* in;
    float* out;
    size_t base;
    if (b < 8192)       { in = iR; out = oR; base = (size_t)b * 1024; }
    else if (b < 12288) { in = iQ; out = oQ; base = (size_t)(b - 8192) * 1024; }
    else if (b < 13312) { in = iK; out = oK; base = (size_t)(b - 12288) * 1024; }
    else                { in = iV; out = oV; base = (size_t)(b - 13312) * 1024; }
    size_t i = base + (size_t)threadIdx.x * 4;
    float4 v = *(const float4*)(in + i);
    uint4 u = {f2tf32(v.x), f2tf32(v.y), f2tf32(v.z), f2tf32(v.w)};
    *(float4*)(out + i) = *(float4*)&u;
}

// ---------------------------------------------------------------------------
// W_O transpose + round: g_WOt[d][feat] = rna(WO[feat][d])
// ---------------------------------------------------------------------------
__global__ __launch_bounds__(256)
void trans_wo(const float* __restrict__ in, float* __restrict__ out) {
    __shared__ float tile[32][33];
    int x = blockIdx.x * 32 + threadIdx.x;
    int y = blockIdx.y * 32 + threadIdx.y;
#pragma unroll
    for (int i = 0; i < 32; i += 8)
        tile[threadIdx.y + i][threadIdx.x] = in[(size_t)(y + i) * DMODEL + x];
    __syncthreads();
    x = blockIdx.y * 32 + threadIdx.x;
    y = blockIdx.x * 32 + threadIdx.y;
#pragma unroll
    for (int i = 0; i < 32; i += 8)
        out[(size_t)(y + i) * DMODEL + x] =
            __uint_as_float(f2tf32(tile[threadIdx.x][threadIdx.y + i]));
}

// ---------------------------------------------------------------------------
// V transpose (per batch): g_Vt[b][feat][tok] = g_V[b*SEQ+tok][feat]
// grid (512/32, 2048/32, 2), block (32,8). Values already tf32-rounded.
// ---------------------------------------------------------------------------
__global__ __launch_bounds__(256)
void trans_v(const float* __restrict__ in, float* __restrict__ out) {
    __shared__ float tile[32][33];
    const float* inb = in + (size_t)blockIdx.z * SEQ * (NKV * DH);
    float* outb = out + (size_t)blockIdx.z * (NKV * DH) * SEQ;
    int x = blockIdx.x * 32 + threadIdx.x;      // feat
    int y = blockIdx.y * 32 + threadIdx.y;      // tok
#pragma unroll
    for (int i = 0; i < 32; i += 8)
        tile[threadIdx.y + i][threadIdx.x] = inb[(size_t)(y + i) * (NKV * DH) + x];
    __syncthreads();
    x = blockIdx.y * 32 + threadIdx.x;          // tok
    y = blockIdx.x * 32 + threadIdx.y;          // feat
#pragma unroll
    for (int i = 0; i < 32; i += 8)
        outb[(size_t)(y + i) * SEQ + x] = tile[threadIdx.x][threadIdx.y + i];
}

// ---------------------------------------------------------------------------
// Shared NT GEMM core (tf32, cp.async double-buffer, LDSM fragment loads).
// C[128,128] tile = A[128,2048] x B[128,2048]^T ; both operands n/m-major.
// ---------------------------------------------------------------------------
#define GLDA 36
#define ABUF (128 * GLDA)

template <bool ROUND_OUT>
__device__ __forceinline__ void gemm_nt_core(const float* __restrict__ Ab,
                                             const float* __restrict__ Bb,
                                             float* __restrict__ C, int Nld,
                                             int rowbase, int colbase) {
    extern __shared__ uint32_t sm[];
    const uint32_t saA = smem_u32(sm);
    const uint32_t saB = saA + 2 * ABUF * 4;

    const int tid = threadIdx.x, ln = tid & 31, wid = tid >> 5;
    const int wm = wid >> 2, wn = wid & 3;
    const int lg = ln >> 2, lt = ln & 3;
    const int arow = (ln & 7) + (((ln >> 3) & 1) << 3);
    const int acol = (ln >> 4) << 2;
    const int brow = (ln & 7) + ((ln >> 4) << 3);
    const int bcol = ((ln >> 3) & 1) << 2;

    float acc[4][4][4];
#pragma unroll
    for (int i = 0; i < 4; i++)
#pragma unroll
        for (int j = 0; j < 4; j++)
#pragma unroll
            for (int r = 0; r < 4; r++) acc[i][j][r] = 0.f;

#define ISSUE(k0, buf)                                                          \
    {                                                                           \
        _Pragma("unroll") for (int i = 0; i < 4; i++) {                         \
            int idx = tid + i * 256;                                            \
            int rw = idx >> 3, cq = (idx & 7) * 4;                              \
            uint32_t so = (uint32_t)(rw * GLDA + cq) * 4;                       \
            cp_async16(saA + (buf) * (ABUF * 4) + so,                           \
                       Ab + (size_t)rw * DMODEL + (k0) + cq);                   \
            cp_async16(saB + (buf) * (ABUF * 4) + so,                           \
                       Bb + (size_t)rw * DMODEL + (k0) + cq);                   \
        }                                                                       \
    }

    ISSUE(0, 0); CP_COMMIT();

    const int nsteps = DMODEL / 32;
    for (int t = 0; t < nsteps; t++) {
        if (t + 1 < nsteps) { ISSUE((t + 1) * 32, (t + 1) & 1); CP_COMMIT(); CP_WAIT(1); }
        else                { CP_WAIT(0); }
        __syncthreads();

        const uint32_t bo = (uint32_t)(t & 1) * (ABUF * 4);
#pragma unroll
        for (int ks = 0; ks < 4; ks++) {
            uint32_t af[4][4];
#pragma unroll
            for (int mi = 0; mi < 4; mi++)
                ldsm4(af[mi], saA + bo +
                      (uint32_t)((wm * 64 + mi * 16 + arow) * GLDA + ks * 8 + acol) * 4);
#pragma unroll
            for (int np = 0; np < 2; np++) {
                uint32_t bf[4];
                ldsm4(bf, saB + bo +
                      (uint32_t)((wn * 32 + np * 16 + brow) * GLDA + ks * 8 + bcol) * 4);
#pragma unroll
                for (int mi = 0; mi < 4; mi++) {
                    mma_tf32(acc[mi][2 * np], af[mi][0], af[mi][1], af[mi][2], af[mi][3],
                             bf[0], bf[1]);
                    mma_tf32(acc[mi][2 * np + 1], af[mi][0], af[mi][1], af[mi][2], af[mi][3],
                             bf[2], bf[3]);
                }
            }
        }
        __syncthreads();
    }
#undef ISSUE

#pragma unroll
    for (int mi = 0; mi < 4; mi++) {
        int row = rowbase + wm * 64 + mi * 16 + lg;
#pragma unroll
        for (int ni = 0; ni < 4; ni++) {
            int col = colbase + wn * 32 + ni * 8 + lt * 2;
            if (ROUND_OUT) {
                uint2 u0 = {f2tf32(acc[mi][ni][0]), f2tf32(acc[mi][ni][1])};
                uint2 u1 = {f2tf32(acc[mi][ni][2]), f2tf32(acc[mi][ni][3])};
                *(uint2*)(C + (size_t)row * Nld + col) = u0;
                *(uint2*)(C + (size_t)(row + 8) * Nld + col) = u1;
            } else {
                *(float2*)(C + (size_t)row * Nld + col) =
                    make_float2(acc[mi][ni][0], acc[mi][ni][1]);
                *(float2*)(C + (size_t)(row + 8) * Nld + col) =
                    make_float2(acc[mi][ni][2], acc[mi][ni][3]);
            }
        }
    }
}

// Fused QKV projection: bx 0..15 -> Q, 16..19 -> K, 20..23 -> V
__global__ __launch_bounds__(256)
void gemm_qkv_tf32(const float* __restrict__ A,
                   const float* __restrict__ WQ, const float* __restrict__ WK,
                   const float* __restrict__ WV,
                   float* __restrict__ Qo, float* __restrict__ Ko,
                   float* __restrict__ Vo) {
    const int bx = blockIdx.x;
    const float* Bmat;
    float* C;
    int N, cb0;
    if (bx < 16)      { Bmat = WQ; C = Qo; N = 2048; cb0 = bx; }
    else if (bx < 20) { Bmat = WK; C = Ko; N = 512;  cb0 = bx - 16; }
    else              { Bmat = WV; C = Vo; N = 512;  cb0 = bx - 20; }
    gemm_nt_core<true>(A + (size_t)(blockIdx.y * 128) * DMODEL,
                       Bmat + (size_t)cb0 * 128 * DMODEL,
                       C, N, blockIdx.y * 128, cb0 * 128);
}

// O projection: out = AO x WOt^T (WOt is [d][feat], n-major)
__global__ __launch_bounds__(256)
void gemm_o_tf32(const float* __restrict__ A, const float* __restrict__ Bt,
                 float* __restrict__ C) {
    gemm_nt_core<false>(A + (size_t)(blockIdx.y * 128) * DMODEL,
                        Bt + (size_t)blockIdx.x * 128 * DMODEL,
                        C, DMODEL, blockIdx.y * 128, blockIdx.x * 128);
}

// ---------------------------------------------------------------------------
// Flash attention, tf32 mma.sync + LDSM fragments. BM=128, K tile 64,
// double-buffered cp.async K/V(transposed), base-2 softmax, LPT.
// SMEM: Ks[2][64][68] VsT[2][64][68] Ps[128][68] = 104,448 B -> 2 CTAs/SM.
// ---------------------------------------------------------------------------
#define ALDS 68
#define KVT (64 * ALDS)
#define KVTB (KVT * 4)
#define NEG_BIG (-1e30f)
#define QSCALE 0.18033688011112042f   /* 0.125 * log2(e) */

__global__ __launch_bounds__(256, 2)
void attn_tf32(const float* __restrict__ Q, const float* __restrict__ K,
               const float* __restrict__ Vt, float* __restrict__ O) {
    extern __shared__ uint32_t sm[];
    const uint32_t ksA = smem_u32(sm);
    const uint32_t vsA = ksA + 2 * KVTB;
    const uint32_t psA = ksA + 4 * KVTB;
    uint32_t* Ps = sm + 4 * KVT;

    const int qt = gridDim.x - 1 - blockIdx.x;   // LPT: heavy first
    const int h = blockIdx.y, b = blockIdx.z;
    const int kvh = h >> 2;
    const int tid = threadIdx.x, ln = tid & 31, wid = tid >> 5;
    const int lg = ln >> 2, lt = ln & 3;
    const int q0 = wid * 16;
    const int arow = (ln & 7) + (((ln >> 3) & 1) << 3);
    const int acol = (ln >> 4) << 2;
    const int brow = (ln & 7) + ((ln >> 4) << 3);
    const int bcol = ((ln >> 3) & 1) << 2;

    const float* Qg = Q + ((size_t)(b * SEQ + qt * 128)) * (NH * DH) + h * DH;
    const float* Kg = K + ((size_t)b * SEQ) * (NKV * DH) + kvh * DH;
    const float* Vg = Vt + ((size_t)(b * (NKV * DH) + kvh * DH)) * SEQ;

    const int ldr = tid >> 4;            // 0..15
    const int ldc = (tid & 15) * 4;      // 16B-aligned word col

    // Q fragments: pre-rounded tf32 * (0.125*log2e), re-rounded (prologue only)
    uint32_t qf[8][4];
    {
        const float* q0p = Qg + (size_t)(q0 + lg) * (NH * DH);
        const float* q1p = Qg + (size_t)(q0 + lg + 8) * (NH * DH);
#pragma unroll
        for (int ks = 0; ks < 8; ks++) {
            int c = ks * 8 + lt;
            qf[ks][0] = f2tf32(__ldg(q0p + c) * QSCALE);
            qf[ks][1] = f2tf32(__ldg(q1p + c) * QSCALE);
            qf[ks][2] = f2tf32(__ldg(q0p + c + 4) * QSCALE);
            qf[ks][3] = f2tf32(__ldg(q1p + c + 4) * QSCALE);
        }
    }

    float m0 = NEG_BIG, m1 = NEG_BIG, l0 = 0.f, l1 = 0.f;
    float acc[8][4];
#pragma unroll
    for (int d = 0; d < 8; d++)
#pragma unroll
        for (int r = 0; r < 4; r++) acc[d][r] = 0.f;

    const int ktmax = 2 * qt + 1;
    const int warp_qlast = qt * 128 + q0 + 15;

#define ISSUE_KV(kt_, buf_)                                                     \
    {                                                                           \
        _Pragma("unroll") for (int i = 0; i < 4; i++) {                         \
            int r = ldr + i * 16;                                               \
            uint32_t so = (uint32_t)(r * ALDS + ldc) * 4;                       \
            cp_async16(ksA + (buf_) * KVTB + so,                                \
                       Kg + (size_t)((kt_) * 64 + r) * (NKV * DH) + ldc);       \
            cp_async16(vsA + (buf_) * KVTB + so,                                \
                       Vg + (size_t)r * SEQ + (kt_) * 64 + ldc);                \
        }                                                                       \
    }

    ISSUE_KV(0, 0); CP_COMMIT();

    for (int kt = 0; kt <= ktmax; kt++) {
        const int bsel = kt & 1;
        if (kt < ktmax) { ISSUE_KV(kt + 1, bsel ^ 1); CP_COMMIT(); CP_WAIT(1); }
        else            { CP_WAIT(0); }
        __syncthreads();     // tile kt visible to all warps

        const uint32_t kbA = ksA + bsel * KVTB;
        const uint32_t vbA = vsA + bsel * KVTB;

        if (kt * 64 <= warp_qlast) {      // tile not fully masked for this warp
            float sc[8][4];
#pragma unroll
            for (int ni = 0; ni < 8; ni++)
#pragma unroll
                for (int r = 0; r < 4; r++) sc[ni][r] = 0.f;
#pragma unroll
            for (int ks = 0; ks < 8; ks++) {
#pragma unroll
                for (int np = 0; np < 4; np++) {
                    uint32_t kf[4];
                    ldsm4(kf, kbA + (uint32_t)((np * 16 + brow) * ALDS + ks * 8 + bcol) * 4);
                    mma_tf32(sc[2 * np], qf[ks][0], qf[ks][1], qf[ks][2], qf[ks][3],
                             kf[0], kf[1]);
                    mma_tf32(sc[2 * np + 1], qf[ks][0], qf[ks][1], qf[ks][2], qf[ks][3],
                             kf[2], kf[3]);
                }
            }

            if (kt * 64 + 63 > qt * 128 + q0) {   // diagonal: causal mask
                int r0g = qt * 128 + q0 + lg, r1g = r0g + 8;
#pragma unroll
                for (int ni = 0; ni < 8; ni++) {
                    int cg = kt * 64 + ni * 8 + lt * 2;
                    if (cg > r0g) sc[ni][0] = NEG_BIG;
                    if (cg + 1 > r0g) sc[ni][1] = NEG_BIG;
                    if (cg > r1g) sc[ni][2] = NEG_BIG;
                    if (cg + 1 > r1g) sc[ni][3] = NEG_BIG;
                }
            }

            // online softmax in base-2: rows (q0+lg), (q0+lg+8)
            float mx0 = NEG_BIG, mx1 = NEG_BIG;
#pragma unroll
            for (int ni = 0; ni < 8; ni++) {
                mx0 = fmaxf(mx0, fmaxf(sc[ni][0], sc[ni][1]));
                mx1 = fmaxf(mx1, fmaxf(sc[ni][2], sc[ni][3]));
            }
            mx0 = fmaxf(mx0, __shfl_xor_sync(0xffffffffu, mx0, 1));
            mx0 = fmaxf(mx0, __shfl_xor_sync(0xffffffffu, mx0, 2));
            mx1 = fmaxf(mx1, __shfl_xor_sync(0xffffffffu, mx1, 1));
            mx1 = fmaxf(mx1, __shfl_xor_sync(0xffffffffu, mx1, 2));
            float nm0 = fmaxf(m0, mx0), nm1 = fmaxf(m1, mx1);
            float corr0 = exp2f(m0 - nm0), corr1 = exp2f(m1 - nm1);
            m0 = nm0; m1 = nm1;

            float s0 = 0.f, s1 = 0.f;
            int pr0 = (q0 + lg) * ALDS, pr1 = (q0 + lg + 8) * ALDS;
#pragma unroll
            for (int ni = 0; ni < 8; ni++) {
                int c = ni * 8 + lt * 2;
                float p00 = exp2f(sc[ni][0] - m0), p01 = exp2f(sc[ni][1] - m0);
                float p10 = exp2f(sc[ni][2] - m1), p11 = exp2f(sc[ni][3] - m1);
                s0 += p00 + p01; s1 += p10 + p11;
                uint2 u0 = {f2tf32(p00), f2tf32(p01)};
                uint2 u1 = {f2tf32(p10), f2tf32(p11)};
                *(uint2*)&Ps[pr0 + c] = u0;
                *(uint2*)&Ps[pr1 + c] = u1;
            }
            s0 += __shfl_xor_sync(0xffffffffu, s0, 1);
            s0 += __shfl_xor_sync(0xffffffffu, s0, 2);
            s1 += __shfl_xor_sync(0xffffffffu, s1, 1);
            s1 += __shfl_xor_sync(0xffffffffu, s1, 2);
            l0 = l0 * corr0 + s0;
            l1 = l1 * corr1 + s1;
#pragma unroll
            for (int d = 0; d < 8; d++) {
                acc[d][0] *= corr0; acc[d][1] *= corr0;
                acc[d][2] *= corr1; acc[d][3] *= corr1;
            }
            __syncwarp();

            // acc += P V  (P rows warp-private; V^T n-major -> LDSM)
#pragma unroll
            for (int ks = 0; ks < 8; ks++) {
                uint32_t pf[4];
                ldsm4(pf, psA + (uint32_t)((q0 + arow) * ALDS + ks * 8 + acol) * 4);
#pragma unroll
                for (int dp = 0; dp < 4; dp++) {
                    uint32_t vf[4];
                    ldsm4(vf, vbA + (uint32_t)((dp * 16 + brow) * ALDS + ks * 8 + bcol) * 4);
                    mma_tf32(acc[2 * dp], pf[0], pf[1], pf[2], pf[3], vf[0], vf[1]);
                    mma_tf32(acc[2 * dp + 1], pf[0], pf[1], pf[2], pf[3], vf[2], vf[3]);
                }
            }
        }
        __syncthreads();   // close reads of buffer bsel before reissue
    }
#undef ISSUE_KV

    // epilogue: normalize, round to tf32 (feeds the O-projection)
    float inv0 = 1.f / l0, inv1 = 1.f / l1;
    float* Og = O + ((size_t)(b * SEQ + qt * 128 + q0 + lg)) * (NH * DH) + h * DH;
#pragma unroll
    for (int di = 0; di < 8; di++) {
        int c = di * 8 + lt * 2;
        uint2 u0 = {f2tf32(acc[di][0] * inv0), f2tf32(acc[di][1] * inv0)};
        uint2 u1 = {f2tf32(acc[di][2] * inv1), f2tf32(acc[di][3] * inv1)};
        *(uint2*)(Og + c) = u0;
        *(uint2*)(Og + (size_t)8 * (NH * DH) + c) = u1;
    }
}

// ---------------------------------------------------------------------------
// kernel_launch
// ---------------------------------------------------------------------------
extern "C" void kernel_launch(void* const* d_in, const int* in_sizes, int n_in,
                              void* d_out, int out_size) {
    const float* residual = (const float*)d_in[0];
    const float* WQ = (const float*)d_in[1];
    const float* WK = (const float*)d_in[2];
    const float* WV = (const float*)d_in[3];
    const float* WO = (const float*)d_in[4];
    float* out = (float*)d_out;

    float *Qb, *Kb, *Vb, *Vtb, *AOb, *RESb, *WQb, *WKb, *WVb, *WOtb;
    cudaGetSymbolAddress((void**)&Qb, g_Q);
    cudaGetSymbolAddress((void**)&Kb, g_K);
    cudaGetSymbolAddress((void**)&Vb, g_V);
    cudaGetSymbolAddress((void**)&Vtb, g_Vt);
    cudaGetSymbolAddress((void**)&AOb, g_AO);
    cudaGetSymbolAddress((void**)&RESb, g_RES);
    cudaGetSymbolAddress((void**)&WQb, g_WQr);
    cudaGetSymbolAddress((void**)&WKb, g_WKr);
    cudaGetSymbolAddress((void**)&WVb, g_WVr);
    cudaGetSymbolAddress((void**)&WOtb, g_WOt);

    size_t smem_g = (size_t)4 * ABUF * 4;                   // 73,728 B
    size_t smem_at = ((size_t)4 * KVT + 128 * ALDS) * 4;    // 104,448 B
    static int attrs_set = 0;
    if (!attrs_set) {
        cudaFuncSetAttribute(gemm_qkv_tf32, cudaFuncAttributeMaxDynamicSharedMemorySize, (int)smem_g);
        cudaFuncSetAttribute(gemm_o_tf32, cudaFuncAttributeMaxDynamicSharedMemorySize, (int)smem_g);
        cudaFuncSetAttribute(attn_tf32, cudaFuncAttributeMaxDynamicSharedMemorySize, (int)smem_at);
        attrs_set = 1;
    }

    // pre-round inputs (residual, WQ, WK, WV) + transpose/round W_O
    round4_tf32<<<14336, 256>>>(residual, WQ, WK, WV, RESb, WQb, WKb, WVb);
    trans_wo<<<dim3(64, 64), dim3(32, 8)>>>(WO, WOtb);

    gemm_qkv_tf32<<<dim3(24, T_TOK / 128), 256, smem_g>>>(
        RESb, WQb, WKb, WVb, Qb, Kb, Vb);

    trans_v<<<dim3(16, 64, 2), dim3(32, 8)>>>(Vb, Vtb);

    attn_tf32<<<dim3(SEQ / 128, NH, 2), 256, smem_at>>>(Qb, Kb, Vtb, AOb);

    gemm_o_tf32<<<dim3(DMODEL / 128, T_TOK / 128), 256, smem_g>>>(
        AOb, WOtb, out);
}